// round 16
// baseline (speedup 1.0000x reference)
#include <cuda_runtime.h>
#include <cstdint>

#define N_NODES   100000
#define N_EDGES   1200000
#define NODE_DIM  64
#define NUM_LAYERS 3
#define NUM_GRAPHS 256
#define R_HID     128
#define R_OUT     32

#define NN (N_NODES * NODE_DIM)
#define POOL_SEG 4
#define CAP 64   // neighbor-bucket capacity (Poisson(12): max deg ~35 over 100k)

// ---- scratch (__device__ globals: allocation-free rule) ----
__device__ float g_h[NUM_LAYERS][NN];              // per-layer GIN outputs (fp32)
__device__ float g_poolp[POOL_SEG][NUM_GRAPHS * NUM_LAYERS * NODE_DIM];
__device__ int   g_cnt[N_NODES];                   // zero-init; re-zeroed by pool_kernel
__device__ int   g_csrc[N_NODES * CAP];            // bucketed src lists per dst

// ---------------------------------------------------------------------------
// Bucket fill: one spread atomicAdd per edge + scattered 4B store.
// ---------------------------------------------------------------------------
__global__ void __launch_bounds__(256)
fill_kernel(const int* __restrict__ src, const int* __restrict__ dst)
{
    int e = blockIdx.x * 256 + threadIdx.x;
    if (e < N_EDGES) {
        int d = __ldg(&dst[e]);
        int pos = atomicAdd(&g_cnt[d], 1);
        if (pos < CAP) g_csrc[d * CAP + pos] = __ldg(&src[e]);
    }
}

// ---------------------------------------------------------------------------
// FUSED GIN layer: h_out = relu(((1+eps)*h + sum_{s in N(n)} h[s]) @ W + b)
//
// Phase 1 (gather, R9-agg layout): 256 threads = 16 nodes x 16 lanes per
// pass, 8 passes for the 128-node tile. Each lane gathers one float4 of
// each neighbor's 256B row (fully coalesced), x4-unrolled accumulators,
// adds the (1+eps) self term, writes DIRECTLY into the smem A-tile
// (pitch-76 floats = float4 pitch 19). No g_comb round-trip.
//
// Phase 2 (GEMM, R9 core): thread = 4 nodes x 8 cols; conflict-free A
// loads via stride-32 node interleave; W broadcast via float4 LDS.128.
// Dynamic smem: 4096 + 64 + 128*76 floats = 55552 B.
// ---------------------------------------------------------------------------
#define APITCH4 19

__global__ void __launch_bounds__(256)
gin_fused_kernel(const float4* __restrict__ h4,     // layer input (gather + self)
                 const float4* __restrict__ W4,
                 const float* __restrict__ b,
                 const float* __restrict__ eps_l,
                 float4* __restrict__ hout4)
{
    extern __shared__ float sm[];
    float* sW = sm;              // [64][64]
    float* sB = sm + 4096;       // [64]
    float* sA = sB + 64;         // [128][76]

    const int tid = threadIdx.x;
    const int nodeBase = blockIdx.x * 128;
    const float eps1 = 1.0f + __ldg(eps_l);

    float4* sW4 = reinterpret_cast<float4*>(sW);
    float4* sA4 = reinterpret_cast<float4*>(sA);

    for (int i = tid; i < 1024; i += 256) sW4[i] = __ldg(&W4[i]);
    if (tid < 64) sB[tid] = __ldg(&b[tid]);

    // ---- Phase 1: gather + self directly into sA ----
    {
        const int glane = tid & 15;          // float4 slot within node row
        const int gnode = tid >> 4;          // node offset within 16-node group
        #pragma unroll 1
        for (int g = 0; g < 8; g++) {
            int nloc = g * 16 + gnode;
            int node = nodeBase + nloc;
            float4 outv = {0.f, 0.f, 0.f, 0.f};
            if (node < N_NODES) {
                int deg = __ldg(&g_cnt[node]);
                if (deg > CAP) deg = CAP;
                const int* __restrict__ row = &g_csrc[node * CAP];

                float4 a0 = {0.f,0.f,0.f,0.f}, a1 = a0, a2 = a0, a3 = a0;
                int j = 0;
                for (; j + 4 <= deg; j += 4) {
                    int s0 = __ldg(&row[j + 0]);
                    int s1 = __ldg(&row[j + 1]);
                    int s2 = __ldg(&row[j + 2]);
                    int s3 = __ldg(&row[j + 3]);
                    float4 v0 = __ldg(&h4[(unsigned)s0 * 16u + glane]);
                    float4 v1 = __ldg(&h4[(unsigned)s1 * 16u + glane]);
                    float4 v2 = __ldg(&h4[(unsigned)s2 * 16u + glane]);
                    float4 v3 = __ldg(&h4[(unsigned)s3 * 16u + glane]);
                    a0.x += v0.x; a0.y += v0.y; a0.z += v0.z; a0.w += v0.w;
                    a1.x += v1.x; a1.y += v1.y; a1.z += v1.z; a1.w += v1.w;
                    a2.x += v2.x; a2.y += v2.y; a2.z += v2.z; a2.w += v2.w;
                    a3.x += v3.x; a3.y += v3.y; a3.z += v3.z; a3.w += v3.w;
                }
                for (; j < deg; j++) {
                    int s0 = __ldg(&row[j]);
                    float4 v0 = __ldg(&h4[(unsigned)s0 * 16u + glane]);
                    a0.x += v0.x; a0.y += v0.y; a0.z += v0.z; a0.w += v0.w;
                }
                float4 acc;
                acc.x = (a0.x + a1.x) + (a2.x + a3.x);
                acc.y = (a0.y + a1.y) + (a2.y + a3.y);
                acc.z = (a0.z + a1.z) + (a2.z + a3.z);
                acc.w = (a0.w + a1.w) + (a2.w + a3.w);

                float4 hv = __ldg(&h4[(unsigned)node * 16u + glane]);
                outv.x = fmaf(eps1, hv.x, acc.x);
                outv.y = fmaf(eps1, hv.y, acc.y);
                outv.z = fmaf(eps1, hv.z, acc.z);
                outv.w = fmaf(eps1, hv.w, acc.w);
            }
            sA4[nloc * APITCH4 + glane] = outv;
        }
    }
    __syncthreads();

    // ---- Phase 2: GEMM (R9 core) ----
    const int lane = tid & 31;   // nodes lane, lane+32, lane+64, lane+96
    const int cg   = tid >> 5;   // cols cg*8 .. +7 (warp-uniform)

    float acc[4][8];
    #pragma unroll
    for (int n = 0; n < 4; n++)
        #pragma unroll
        for (int c = 0; c < 8; c++)
            acc[n][c] = sB[cg * 8 + c];

    #pragma unroll 4
    for (int k4 = 0; k4 < 16; k4++) {
        float4 a[4];
        #pragma unroll
        for (int n = 0; n < 4; n++)
            a[n] = sA4[(lane + n * 32) * APITCH4 + k4];   // conflict-free
        #pragma unroll
        for (int kk = 0; kk < 4; kk++) {
            float4 w0 = sW4[(k4 * 4 + kk) * 16 + cg * 2];       // broadcast
            float4 w1 = sW4[(k4 * 4 + kk) * 16 + cg * 2 + 1];   // broadcast
            float wv[8] = {w0.x, w0.y, w0.z, w0.w, w1.x, w1.y, w1.z, w1.w};
            float av[4];
            av[0] = (kk == 0) ? a[0].x : (kk == 1) ? a[0].y : (kk == 2) ? a[0].z : a[0].w;
            av[1] = (kk == 0) ? a[1].x : (kk == 1) ? a[1].y : (kk == 2) ? a[1].z : a[1].w;
            av[2] = (kk == 0) ? a[2].x : (kk == 1) ? a[2].y : (kk == 2) ? a[2].z : a[2].w;
            av[3] = (kk == 0) ? a[3].x : (kk == 1) ? a[3].y : (kk == 2) ? a[3].z : a[3].w;
            #pragma unroll
            for (int n = 0; n < 4; n++)
                #pragma unroll
                for (int c = 0; c < 8; c++)
                    acc[n][c] = fmaf(av[n], wv[c], acc[n][c]);
        }
    }

    #pragma unroll
    for (int n = 0; n < 4; n++) {
        int node = nodeBase + lane + n * 32;
        if (node < N_NODES) {
            float4 o0, o1;
            o0.x = fmaxf(acc[n][0], 0.f); o0.y = fmaxf(acc[n][1], 0.f);
            o0.z = fmaxf(acc[n][2], 0.f); o0.w = fmaxf(acc[n][3], 0.f);
            o1.x = fmaxf(acc[n][4], 0.f); o1.y = fmaxf(acc[n][5], 0.f);
            o1.z = fmaxf(acc[n][6], 0.f); o1.w = fmaxf(acc[n][7], 0.f);
            hout4[node * 16 + cg * 2]     = o0;
            hout4[node * 16 + cg * 2 + 1] = o1;
        }
    }
}

// ---------------------------------------------------------------------------
// Graph pooling, 4 segments per graph (deterministic partials, no atomics).
// Also re-zeroes g_cnt for the next graph replay (1024*192 threads >= N_NODES).
// ---------------------------------------------------------------------------
__global__ void __launch_bounds__(192)
pool_kernel(const int* __restrict__ gids)
{
    int zid = blockIdx.x * 192 + threadIdx.x;
    if (zid < N_NODES) g_cnt[zid] = 0;

    const int b = blockIdx.x >> 2;
    const int seg = blockIdx.x & 3;
    const int j = threadIdx.x;

    int lo = 0, hi = N_NODES;
    while (lo < hi) { int m = (lo + hi) >> 1; if (__ldg(&gids[m]) < b) lo = m + 1; else hi = m; }
    const int start = lo;
    hi = N_NODES;
    while (lo < hi) { int m = (lo + hi) >> 1; if (__ldg(&gids[m]) < b + 1) lo = m + 1; else hi = m; }
    const int end = lo;

    const int len = end - start;
    const int s0 = start + (len * seg) / POOL_SEG;
    const int s1 = start + (len * (seg + 1)) / POOL_SEG;

    const int l = j >> 6;
    const int d = j & 63;
    const float* __restrict__ hb = g_h[l];

    float a0 = 0.f, a1 = 0.f, a2 = 0.f, a3 = 0.f;
    int n = s0;
    for (; n + 3 < s1; n += 4) {
        a0 += __ldg(&hb[(n + 0) * 64 + d]);
        a1 += __ldg(&hb[(n + 1) * 64 + d]);
        a2 += __ldg(&hb[(n + 2) * 64 + d]);
        a3 += __ldg(&hb[(n + 3) * 64 + d]);
    }
    for (; n < s1; n++) a0 += __ldg(&hb[n * 64 + d]);
    g_poolp[seg][b * (NUM_LAYERS * NODE_DIM) + j] = (a0 + a1) + (a2 + a3);
}

// ---------------------------------------------------------------------------
// Readout MLP: out = relu(g @ W1 + b1) @ W2 + b2 (sums the 4 pool partials)
// ---------------------------------------------------------------------------
__global__ void __launch_bounds__(128)
readout_kernel(const float* __restrict__ W1, const float* __restrict__ b1,
               const float* __restrict__ W2, const float* __restrict__ b2,
               float* __restrict__ out)
{
    const int b = blockIdx.x;
    const int tid = threadIdx.x;
    __shared__ float sg[NUM_LAYERS * NODE_DIM];
    __shared__ float sh[R_HID];

    for (int i = tid; i < NUM_LAYERS * NODE_DIM; i += 128) {
        int gi = b * (NUM_LAYERS * NODE_DIM) + i;
        sg[i] = (g_poolp[0][gi] + g_poolp[1][gi]) + (g_poolp[2][gi] + g_poolp[3][gi]);
    }
    __syncthreads();

    float acc = __ldg(&b1[tid]);
    #pragma unroll 8
    for (int k = 0; k < NUM_LAYERS * NODE_DIM; k++)
        acc = fmaf(sg[k], __ldg(&W1[k * R_HID + tid]), acc);
    sh[tid] = fmaxf(acc, 0.0f);
    __syncthreads();

    if (tid < R_OUT) {
        float o = __ldg(&b2[tid]);
        #pragma unroll 8
        for (int k = 0; k < R_HID; k++)
            o = fmaf(sh[k], __ldg(&W2[k * R_OUT + tid]), o);
        out[b * R_OUT + tid] = o;
    }
}

// ---------------------------------------------------------------------------
extern "C" void kernel_launch(void* const* d_in, const int* in_sizes, int n_in,
                              void* d_out, int out_size)
{
    const float* x     = (const float*)d_in[0];
    const float* gin_W = (const float*)d_in[1];
    const float* gin_b = (const float*)d_in[2];
    const float* eps   = (const float*)d_in[3];
    const float* r_W1  = (const float*)d_in[4];
    const float* r_b1  = (const float*)d_in[5];
    const float* r_W2  = (const float*)d_in[6];
    const float* r_b2  = (const float*)d_in[7];
    const int*   src   = (const int*)d_in[8];
    const int*   dst   = (const int*)d_in[9];
    const int*   gids  = (const int*)d_in[10];
    float* out = (float*)d_out;

    void* hsym = nullptr;
    cudaGetSymbolAddress(&hsym, g_h);
    float* hbase = (float*)hsym;

    const int GIN_SMEM = (4096 + 64 + 128 * 76) * (int)sizeof(float);  // 55552 B
    cudaFuncSetAttribute(gin_fused_kernel, cudaFuncAttributeMaxDynamicSharedMemorySize, GIN_SMEM);

    const int E_BLOCKS   = (N_EDGES + 255) / 256;   // 4688
    const int GIN_BLOCKS = (N_NODES + 127) / 128;   // 782

    // single-kernel adjacency build (g_cnt zero: module init on call 1,
    // pool_kernel re-zeroes at the end of every call)
    fill_kernel<<<E_BLOCKS, 256>>>(src, dst);

    for (int l = 0; l < NUM_LAYERS; l++) {
        const float* hin = (l == 0) ? x : (hbase + (size_t)(l - 1) * NN);
        gin_fused_kernel<<<GIN_BLOCKS, 256, GIN_SMEM>>>(
            (const float4*)hin,
            (const float4*)(gin_W + (size_t)l * 64 * 64),
            gin_b + (size_t)l * 64,
            eps + l,
            (float4*)(hbase + (size_t)l * NN));
    }
    pool_kernel<<<NUM_GRAPHS * POOL_SEG, NUM_LAYERS * NODE_DIM>>>(gids);
    readout_kernel<<<NUM_GRAPHS, R_HID>>>(r_W1, r_b1, r_W2, r_b2, out);
}